// round 1
// baseline (speedup 1.0000x reference)
#include <cuda_runtime.h>
#include <math.h>

#define N_TOK 2304

// Scratch (device globals: allocation-free per harness rules)
__device__ float g_qkv[2u * 1536u * 2304u];   // (B, 3*512, N)
__device__ float g_inv[2 * 1024];             // inverse L2 norms for q (0..511) and k (512..1023) rows
__device__ float g_att[2u * 512u * 2304u];    // attention output (B, 512, N)

// ---------------------------------------------------------------------------
// Generic batched GEMM: Y[b][m][n] = sum_k W[m][k] * X[b][k][n] (+ bias[m])
// M = gridDim.y*64, N = 2304, K param. 64x64 tiles, K-step 16, 4x4 micro.
// ---------------------------------------------------------------------------
__global__ void gemm64(const float* __restrict__ W, const float* __restrict__ X,
                       const float* __restrict__ bias, float* __restrict__ Y, int K) {
    __shared__ float As[16][64];
    __shared__ float Bs[16][64];
    const int tid = threadIdx.x;
    const int tx = tid & 15, ty = tid >> 4;
    const int n0 = blockIdx.x * 64;
    const int m0 = blockIdx.y * 64;
    const int b  = blockIdx.z;
    const float* Xb = X + (size_t)b * K * N_TOK;
    float* Yb = Y + (size_t)b * gridDim.y * 64 * N_TOK;

    float acc[4][4] = {};
    const int mm = tid >> 2, kg = tid & 3;   // A-load mapping
    const int lk = tid >> 4, ln = tid & 15;  // B-load mapping

    for (int k0 = 0; k0 < K; k0 += 16) {
        float4 w4 = *(const float4*)(W + (size_t)(m0 + mm) * K + k0 + kg * 4);
        As[kg * 4 + 0][mm] = w4.x;
        As[kg * 4 + 1][mm] = w4.y;
        As[kg * 4 + 2][mm] = w4.z;
        As[kg * 4 + 3][mm] = w4.w;
        *(float4*)(&Bs[lk][ln * 4]) =
            *(const float4*)(Xb + (size_t)(k0 + lk) * N_TOK + n0 + ln * 4);
        __syncthreads();
#pragma unroll
        for (int k = 0; k < 16; k++) {
            float4 a  = *(const float4*)(&As[k][ty * 4]);
            float4 bb = *(const float4*)(&Bs[k][tx * 4]);
            float av[4] = {a.x, a.y, a.z, a.w};
            float bv[4] = {bb.x, bb.y, bb.z, bb.w};
#pragma unroll
            for (int r = 0; r < 4; r++)
#pragma unroll
                for (int c = 0; c < 4; c++)
                    acc[r][c] = fmaf(av[r], bv[c], acc[r][c]);
        }
        __syncthreads();
    }
#pragma unroll
    for (int r = 0; r < 4; r++) {
        float bv = bias ? bias[m0 + ty * 4 + r] : 0.f;
        float4 o = make_float4(acc[r][0] + bv, acc[r][1] + bv,
                               acc[r][2] + bv, acc[r][3] + bv);
        *(float4*)(Yb + (size_t)(m0 + ty * 4 + r) * N_TOK + n0 + tx * 4) = o;
    }
}

// ---------------------------------------------------------------------------
// Row L2-norm inverse: one block per (b, o) row of q/k part of g_qkv.
// row = b*1024 + o, o in [0,1024): o<512 -> q rows, o>=512 -> k rows.
// ---------------------------------------------------------------------------
__global__ void norm_k(const float* __restrict__ qkv, float* __restrict__ inv) {
    const int row = blockIdx.x;            // 0..2047
    const int b = row >> 10, o = row & 1023;
    const float* p = qkv + ((size_t)b * 1536 + o) * N_TOK;
    float ss = 0.f;
    for (int i = threadIdx.x; i < N_TOK; i += 256) {
        float v = p[i];
        ss += v * v;
    }
#pragma unroll
    for (int off = 16; off; off >>= 1)
        ss += __shfl_xor_sync(0xffffffffu, ss, off);
    __shared__ float red[8];
    if ((threadIdx.x & 31) == 0) red[threadIdx.x >> 5] = ss;
    __syncthreads();
    if (threadIdx.x == 0) {
        float t = 0.f;
#pragma unroll
        for (int i = 0; i < 8; i++) t += red[i];
        inv[row] = 1.f / fmaxf(sqrtf(t), 1e-12f);
    }
}

// ---------------------------------------------------------------------------
// Flash attention, fp32. Block: 64 query tokens of one (b,h). 256 threads.
// S[i][j] = sum_d qn[d][i]*kn[d][j]; online softmax over j; O = P @ V^T.
// ---------------------------------------------------------------------------
__global__ void attn64(const float* __restrict__ qkv, const float* __restrict__ inv,
                       float* __restrict__ out) {
    extern __shared__ float sm[];
    float* Qs = sm;              // [64][64]   stride 64
    float* Ks = Qs + 64 * 64;    // [64][64]   stride 64
    float* Vs = Ks + 64 * 64;    // [64][65]   stride 65 (conflict pad)
    float* Ps = Vs + 64 * 65;    // [64][65]   stride 65 (conflict pad)

    const int tid = threadIdx.x;
    const int tx = tid & 15, ty = tid >> 4;
    const int n0 = blockIdx.x * 64;
    const int h = blockIdx.y, b = blockIdx.z;

    const float* qb = qkv + ((size_t)b * 1536 + h * 64) * N_TOK;
    const float* kb = qb + (size_t)512 * N_TOK;
    const float* vb = qb + (size_t)1024 * N_TOK;
    const float* invq = inv + b * 1024 + h * 64;
    const float* invk = invq + 512;

    const int j4 = tid & 15, d0 = tid >> 4;

    // Load + scale Q tile (resident for whole block)
    for (int d = d0; d < 64; d += 16) {
        float4 t = *(const float4*)(qb + (size_t)d * N_TOK + n0 + j4 * 4);
        float s = invq[d];
        float4 r = make_float4(t.x * s, t.y * s, t.z * s, t.w * s);
        *(float4*)(Qs + d * 64 + j4 * 4) = r;
    }

    float O[4][4] = {};
    float mrow[4] = {-1e30f, -1e30f, -1e30f, -1e30f};
    float lrow[4] = {};
    __syncthreads();

    for (int m0 = 0; m0 < N_TOK; m0 += 64) {
        // Load K (scaled) and V tiles
        for (int d = d0; d < 64; d += 16) {
            float4 t = *(const float4*)(kb + (size_t)d * N_TOK + m0 + j4 * 4);
            float s = invk[d];
            float4 r = make_float4(t.x * s, t.y * s, t.z * s, t.w * s);
            *(float4*)(Ks + d * 64 + j4 * 4) = r;
            float4 v = *(const float4*)(vb + (size_t)d * N_TOK + m0 + j4 * 4);
            Vs[d * 65 + j4 * 4 + 0] = v.x;
            Vs[d * 65 + j4 * 4 + 1] = v.y;
            Vs[d * 65 + j4 * 4 + 2] = v.z;
            Vs[d * 65 + j4 * 4 + 3] = v.w;
        }
        __syncthreads();

        // S = Q^T K  (rows i = 4ty+r, cols j = 4tx+c)
        float s4[4][4] = {};
#pragma unroll 8
        for (int d = 0; d < 64; d++) {
            float4 a  = *(const float4*)(Qs + d * 64 + ty * 4);
            float4 bq = *(const float4*)(Ks + d * 64 + tx * 4);
            float av[4] = {a.x, a.y, a.z, a.w};
            float bv[4] = {bq.x, bq.y, bq.z, bq.w};
#pragma unroll
            for (int r = 0; r < 4; r++)
#pragma unroll
                for (int c = 0; c < 4; c++)
                    s4[r][c] = fmaf(av[r], bv[c], s4[r][c]);
        }

        // Online softmax per row (row group = 16 lanes with same ty)
#pragma unroll
        for (int r = 0; r < 4; r++) {
            float mx = fmaxf(fmaxf(s4[r][0], s4[r][1]), fmaxf(s4[r][2], s4[r][3]));
#pragma unroll
            for (int off = 8; off; off >>= 1)
                mx = fmaxf(mx, __shfl_xor_sync(0xffffffffu, mx, off));
            float mnew = fmaxf(mrow[r], mx);
            float corr = __expf(mrow[r] - mnew);
            mrow[r] = mnew;
            float ps = 0.f;
#pragma unroll
            for (int c = 0; c < 4; c++) {
                float p = __expf(s4[r][c] - mnew);
                s4[r][c] = p;
                ps += p;
            }
#pragma unroll
            for (int off = 8; off; off >>= 1)
                ps += __shfl_xor_sync(0xffffffffu, ps, off);
            lrow[r] = lrow[r] * corr + ps;
#pragma unroll
            for (int c = 0; c < 4; c++) O[r][c] *= corr;
#pragma unroll
            for (int c = 0; c < 4; c++)
                Ps[(ty * 4 + r) * 65 + tx * 4 + c] = s4[r][c];
        }
        __syncthreads();

        // O[i][d] += sum_j P[i][j] * V[d][j]; columns d = 16c + tx (bank-spread)
#pragma unroll 4
        for (int j = 0; j < 64; j++) {
            float p0 = Ps[(ty * 4 + 0) * 65 + j];
            float p1 = Ps[(ty * 4 + 1) * 65 + j];
            float p2 = Ps[(ty * 4 + 2) * 65 + j];
            float p3 = Ps[(ty * 4 + 3) * 65 + j];
            float v0 = Vs[(tx)      * 65 + j];
            float v1 = Vs[(tx + 16) * 65 + j];
            float v2 = Vs[(tx + 32) * 65 + j];
            float v3 = Vs[(tx + 48) * 65 + j];
            O[0][0] = fmaf(p0, v0, O[0][0]); O[0][1] = fmaf(p0, v1, O[0][1]);
            O[0][2] = fmaf(p0, v2, O[0][2]); O[0][3] = fmaf(p0, v3, O[0][3]);
            O[1][0] = fmaf(p1, v0, O[1][0]); O[1][1] = fmaf(p1, v1, O[1][1]);
            O[1][2] = fmaf(p1, v2, O[1][2]); O[1][3] = fmaf(p1, v3, O[1][3]);
            O[2][0] = fmaf(p2, v0, O[2][0]); O[2][1] = fmaf(p2, v1, O[2][1]);
            O[2][2] = fmaf(p2, v2, O[2][2]); O[2][3] = fmaf(p2, v3, O[2][3]);
            O[3][0] = fmaf(p3, v0, O[3][0]); O[3][1] = fmaf(p3, v1, O[3][1]);
            O[3][2] = fmaf(p3, v2, O[3][2]); O[3][3] = fmaf(p3, v3, O[3][3]);
        }
        __syncthreads();
    }

    // Normalize and stage through smem (Ps, stride 65) for coalesced stores
#pragma unroll
    for (int r = 0; r < 4; r++) {
        float rl = 1.f / lrow[r];
#pragma unroll
        for (int c = 0; c < 4; c++)
            Ps[(c * 16 + tx) * 65 + ty * 4 + r] = O[r][c] * rl;
    }
    __syncthreads();
    float* ob = out + ((size_t)b * 512 + h * 64) * N_TOK;
    for (int d = d0; d < 64; d += 16) {
        float4 t = make_float4(Ps[d * 65 + j4 * 4 + 0], Ps[d * 65 + j4 * 4 + 1],
                               Ps[d * 65 + j4 * 4 + 2], Ps[d * 65 + j4 * 4 + 3]);
        *(float4*)(ob + (size_t)d * N_TOK + n0 + j4 * 4) = t;
    }
}

// ---------------------------------------------------------------------------
extern "C" void kernel_launch(void* const* d_in, const int* in_sizes, int n_in,
                              void* d_out, int out_size) {
    (void)in_sizes; (void)n_in; (void)out_size;
    const float* x      = (const float*)d_in[0];
    const float* w_qkv  = (const float*)d_in[1];
    const float* w_proj = (const float*)d_in[2];
    const float* b_proj = (const float*)d_in[3];
    float* y = (float*)d_out;

    float *qkv_p = nullptr, *inv_p = nullptr, *att_p = nullptr;
    cudaGetSymbolAddress((void**)&qkv_p, g_qkv);
    cudaGetSymbolAddress((void**)&inv_p, g_inv);
    cudaGetSymbolAddress((void**)&att_p, g_att);

    const int attn_smem = (64 * 64 * 2 + 64 * 65 * 2) * 4;  // 66048 B
    cudaFuncSetAttribute(attn64, cudaFuncAttributeMaxDynamicSharedMemorySize,
                         attn_smem);

    // 1) qkv = w_qkv @ x   (M=1536, K=256, N=2304, B=2)
    gemm64<<<dim3(36, 24, 2), 256>>>(w_qkv, x, nullptr, qkv_p, 256);
    // 2) per-(b,h,d) inverse L2 norms over tokens for q and k
    norm_k<<<2048, 256>>>(qkv_p, inv_p);
    // 3) attention -> g_att (B, 512, N)
    attn64<<<dim3(36, 8, 2), 256, attn_smem>>>(qkv_p, inv_p, att_p);
    // 4) y = w_proj @ att + b_proj   (M=256, K=512, N=2304, B=2)
    gemm64<<<dim3(36, 4, 2), 256>>>(w_proj, att_p, b_proj, y, 512);
}

// round 2
// speedup vs baseline: 2.6789x; 2.6789x over previous
#include <cuda_runtime.h>
#include <math.h>

#define N_TOK 2304

// Scratch (device globals: allocation-free per harness rules)
__device__ float g_qkv[2u * 1536u * 2304u];   // (B, 3*512, N)
__device__ float g_inv[2 * 1024];             // inv L2 norms: q rows 0..511, k rows 512..1023
__device__ float g_att[2u * 512u * 2304u];    // attention output (B, 512, N)

__device__ __forceinline__ float to_tf32(float x) {
    float r;
    asm("cvt.rna.tf32.f32 %0, %1;" : "=f"(r) : "f"(x));
    return r;
}
__device__ __forceinline__ unsigned fb(float x) { return __float_as_uint(x); }

__device__ __forceinline__ void mma_tf32(float* d, const unsigned* a, const unsigned* b) {
    asm volatile(
        "mma.sync.aligned.m16n8k8.row.col.f32.tf32.tf32.f32 "
        "{%0,%1,%2,%3}, {%4,%5,%6,%7}, {%8,%9}, {%0,%1,%2,%3};\n"
        : "+f"(d[0]), "+f"(d[1]), "+f"(d[2]), "+f"(d[3])
        : "r"(a[0]), "r"(a[1]), "r"(a[2]), "r"(a[3]), "r"(b[0]), "r"(b[1]));
}

// ---------------------------------------------------------------------------
// tf32 GEMM: Y[b][m][n] = sum_k W[m][k]*X[b][k][n] (+bias[m])
// Block tile 128x64, 8 warps, warp = 16 rows x 64 cols, k-chunk 16.
// ---------------------------------------------------------------------------
__global__ __launch_bounds__(256) void gemm_tf32(
    const float* __restrict__ W, const float* __restrict__ X,
    const float* __restrict__ bias, float* __restrict__ Y, int K, int Mblocks) {
    __shared__ float As[128 * 20];   // [m][kc] stride 20
    __shared__ float Bs[16 * 68];    // [kc][n] stride 68

    const int tid = threadIdx.x, lane = tid & 31, w = tid >> 5;
    const int g = lane >> 2, tg = lane & 3;
    const int n0 = blockIdx.x * 64;
    const int m0 = blockIdx.y * 128;
    const int b  = blockIdx.z;
    const float* Xb = X + (size_t)b * K * N_TOK;
    float* Yb = Y + (size_t)b * Mblocks * 128 * N_TOK;
    const int i0 = w * 16;

    float acc[8][4] = {};

    for (int k0 = 0; k0 < K; k0 += 16) {
        // Stage W tile (128 x 16), tf32-rounded
#pragma unroll
        for (int e = tid; e < 512; e += 256) {
            int m = e >> 2, kg = e & 3;
            float4 t = *(const float4*)(W + (size_t)(m0 + m) * K + k0 + kg * 4);
            float* p = &As[m * 20 + kg * 4];
            p[0] = to_tf32(t.x); p[1] = to_tf32(t.y);
            p[2] = to_tf32(t.z); p[3] = to_tf32(t.w);
        }
        // Stage X tile (16 x 64), tf32-rounded
        {
            int k = tid >> 4, n4 = tid & 15;
            float4 t = *(const float4*)(Xb + (size_t)(k0 + k) * N_TOK + n0 + n4 * 4);
            float* p = &Bs[k * 68 + n4 * 4];
            p[0] = to_tf32(t.x); p[1] = to_tf32(t.y);
            p[2] = to_tf32(t.z); p[3] = to_tf32(t.w);
        }
        __syncthreads();
#pragma unroll
        for (int kc = 0; kc < 16; kc += 8) {
            unsigned a[4];
            a[0] = fb(As[(i0 + g) * 20 + kc + tg]);
            a[1] = fb(As[(i0 + g + 8) * 20 + kc + tg]);
            a[2] = fb(As[(i0 + g) * 20 + kc + tg + 4]);
            a[3] = fb(As[(i0 + g + 8) * 20 + kc + tg + 4]);
#pragma unroll
            for (int nf = 0; nf < 8; nf++) {
                unsigned bb[2];
                bb[0] = fb(Bs[(kc + tg) * 68 + nf * 8 + g]);
                bb[1] = fb(Bs[(kc + tg + 4) * 68 + nf * 8 + g]);
                mma_tf32(acc[nf], a, bb);
            }
        }
        __syncthreads();
    }
    // Epilogue
    float bv0 = bias ? bias[m0 + i0 + g] : 0.f;
    float bv1 = bias ? bias[m0 + i0 + g + 8] : 0.f;
#pragma unroll
    for (int nf = 0; nf < 8; nf++) {
        float2 r0 = make_float2(acc[nf][0] + bv0, acc[nf][1] + bv0);
        float2 r1 = make_float2(acc[nf][2] + bv1, acc[nf][3] + bv1);
        *(float2*)(Yb + (size_t)(m0 + i0 + g) * N_TOK + n0 + nf * 8 + tg * 2) = r0;
        *(float2*)(Yb + (size_t)(m0 + i0 + g + 8) * N_TOK + n0 + nf * 8 + tg * 2) = r1;
    }
}

// ---------------------------------------------------------------------------
// Row L2-norm inverse (as before)
// ---------------------------------------------------------------------------
__global__ void norm_k(const float* __restrict__ qkv, float* __restrict__ inv) {
    const int row = blockIdx.x;            // 0..2047
    const int b = row >> 10, o = row & 1023;
    const float* p = qkv + ((size_t)b * 1536 + o) * N_TOK;
    float ss = 0.f;
    for (int i = threadIdx.x; i < N_TOK; i += 256) {
        float v = p[i];
        ss += v * v;
    }
#pragma unroll
    for (int off = 16; off; off >>= 1)
        ss += __shfl_xor_sync(0xffffffffu, ss, off);
    __shared__ float red[8];
    if ((threadIdx.x & 31) == 0) red[threadIdx.x >> 5] = ss;
    __syncthreads();
    if (threadIdx.x == 0) {
        float t = 0.f;
#pragma unroll
        for (int i = 0; i < 8; i++) t += red[i];
        inv[row] = 1.f / fmaxf(sqrtf(t), 1e-12f);
    }
}

// ---------------------------------------------------------------------------
// Flash attention, tf32 mma. Block = 128 queries of one (b,h), 256 thr, 8 warps.
// Warp w owns S/O rows 16w..16w+15 (full rows -> in-lane softmax state).
// ---------------------------------------------------------------------------
__global__ __launch_bounds__(256, 2) void attn_mma(
    const float* __restrict__ qkv, const float* __restrict__ inv,
    float* __restrict__ out) {
    extern __shared__ float sm[];
    float* Qt = sm;                // [128][68]  Qt[i][d]
    float* Ks = Qt + 128 * 68;     // [64][68]   Ks[d][m]
    float* Vs = Ks + 64 * 68;      // [64][68]   Vs[d][m]
    float* Ps = Vs + 64 * 68;      // [128][68]  Ps[i][m] (also O staging)

    const int tid = threadIdx.x, lane = tid & 31, w = tid >> 5;
    const int g = lane >> 2, tg = lane & 3;
    const int n0 = blockIdx.x * 128;
    const int h = blockIdx.y, b = blockIdx.z;

    const float* qb = qkv + ((size_t)b * 1536 + h * 64) * N_TOK;
    const float* kb = qb + (size_t)512 * N_TOK;
    const float* vb = qb + (size_t)1024 * N_TOK;
    const float* invq = inv + b * 1024 + h * 64;
    const float* invk = invq + 512;
    const int i0 = w * 16;

    // Load Q tile transposed+scaled+tf32: Qt[i][d] = q[d][n0+i]*invq[d]
#pragma unroll
    for (int e = tid; e < 64 * 32; e += 256) {
        int d = e >> 5, i4 = e & 31;
        float4 t = *(const float4*)(qb + (size_t)d * N_TOK + n0 + i4 * 4);
        float s = invq[d];
        Qt[(i4 * 4 + 0) * 68 + d] = to_tf32(t.x * s);
        Qt[(i4 * 4 + 1) * 68 + d] = to_tf32(t.y * s);
        Qt[(i4 * 4 + 2) * 68 + d] = to_tf32(t.z * s);
        Qt[(i4 * 4 + 3) * 68 + d] = to_tf32(t.w * s);
    }

    float O[8][4] = {};
    float m0r = -1e30f, m1r = -1e30f, l0r = 0.f, l1r = 0.f;
    __syncthreads();

    for (int t0 = 0; t0 < N_TOK; t0 += 64) {
        // Stage K (scaled) and V tiles, tf32-rounded
#pragma unroll
        for (int e = tid; e < 64 * 16; e += 256) {
            int d = e >> 4, m4 = e & 15;
            float4 t = *(const float4*)(kb + (size_t)d * N_TOK + t0 + m4 * 4);
            float s = invk[d];
            *(float4*)(&Ks[d * 68 + m4 * 4]) = make_float4(
                to_tf32(t.x * s), to_tf32(t.y * s), to_tf32(t.z * s), to_tf32(t.w * s));
            float4 v = *(const float4*)(vb + (size_t)d * N_TOK + t0 + m4 * 4);
            *(float4*)(&Vs[d * 68 + m4 * 4]) = make_float4(
                to_tf32(v.x), to_tf32(v.y), to_tf32(v.z), to_tf32(v.w));
        }
        __syncthreads();

        // Phase 1: S(16x64) = Qt_rows x K
        float S[8][4] = {};
#pragma unroll
        for (int k0 = 0; k0 < 64; k0 += 8) {
            unsigned a[4];
            a[0] = fb(Qt[(i0 + g) * 68 + k0 + tg]);
            a[1] = fb(Qt[(i0 + g + 8) * 68 + k0 + tg]);
            a[2] = fb(Qt[(i0 + g) * 68 + k0 + tg + 4]);
            a[3] = fb(Qt[(i0 + g + 8) * 68 + k0 + tg + 4]);
#pragma unroll
            for (int nf = 0; nf < 8; nf++) {
                unsigned bb[2];
                bb[0] = fb(Ks[(k0 + tg) * 68 + nf * 8 + g]);
                bb[1] = fb(Ks[(k0 + tg + 4) * 68 + nf * 8 + g]);
                mma_tf32(S[nf], a, bb);
            }
        }

        // Online softmax: rows (i0+g) [c0,c1] and (i0+g+8) [c2,c3]
        float r0 = -1e30f, r1 = -1e30f;
#pragma unroll
        for (int nf = 0; nf < 8; nf++) {
            r0 = fmaxf(r0, fmaxf(S[nf][0], S[nf][1]));
            r1 = fmaxf(r1, fmaxf(S[nf][2], S[nf][3]));
        }
        r0 = fmaxf(r0, __shfl_xor_sync(0xffffffffu, r0, 1));
        r0 = fmaxf(r0, __shfl_xor_sync(0xffffffffu, r0, 2));
        r1 = fmaxf(r1, __shfl_xor_sync(0xffffffffu, r1, 1));
        r1 = fmaxf(r1, __shfl_xor_sync(0xffffffffu, r1, 2));
        float mn0 = fmaxf(m0r, r0), mn1 = fmaxf(m1r, r1);
        float c0 = __expf(m0r - mn0), c1 = __expf(m1r - mn1);
        m0r = mn0; m1r = mn1;
        float s0 = 0.f, s1 = 0.f;
#pragma unroll
        for (int nf = 0; nf < 8; nf++) {
            S[nf][0] = __expf(S[nf][0] - mn0);
            S[nf][1] = __expf(S[nf][1] - mn0);
            S[nf][2] = __expf(S[nf][2] - mn1);
            S[nf][3] = __expf(S[nf][3] - mn1);
            s0 += S[nf][0] + S[nf][1];
            s1 += S[nf][2] + S[nf][3];
        }
        s0 += __shfl_xor_sync(0xffffffffu, s0, 1);
        s0 += __shfl_xor_sync(0xffffffffu, s0, 2);
        s1 += __shfl_xor_sync(0xffffffffu, s1, 1);
        s1 += __shfl_xor_sync(0xffffffffu, s1, 2);
        l0r = l0r * c0 + s0;
        l1r = l1r * c1 + s1;
#pragma unroll
        for (int nf = 0; nf < 8; nf++) {
            O[nf][0] *= c0; O[nf][1] *= c0;
            O[nf][2] *= c1; O[nf][3] *= c1;
            // Write P (tf32) to own rows
            *(float2*)(&Ps[(i0 + g) * 68 + nf * 8 + tg * 2]) =
                make_float2(to_tf32(S[nf][0]), to_tf32(S[nf][1]));
            *(float2*)(&Ps[(i0 + g + 8) * 68 + nf * 8 + tg * 2]) =
                make_float2(to_tf32(S[nf][2]), to_tf32(S[nf][3]));
        }
        __syncwarp();

        // Phase 2: O(16x64) += P(16x64) x V^T(64x64); B[k=m][n=d] = Vs[d][m]
#pragma unroll
        for (int k0 = 0; k0 < 64; k0 += 8) {
            unsigned a[4];
            a[0] = fb(Ps[(i0 + g) * 68 + k0 + tg]);
            a[1] = fb(Ps[(i0 + g + 8) * 68 + k0 + tg]);
            a[2] = fb(Ps[(i0 + g) * 68 + k0 + tg + 4]);
            a[3] = fb(Ps[(i0 + g + 8) * 68 + k0 + tg + 4]);
#pragma unroll
            for (int nf = 0; nf < 8; nf++) {
                unsigned bb[2];
                bb[0] = fb(Vs[(nf * 8 + g) * 68 + k0 + tg]);
                bb[1] = fb(Vs[(nf * 8 + g) * 68 + k0 + tg + 4]);
                mma_tf32(O[nf], a, bb);
            }
        }
        __syncthreads();   // protect Ks/Vs before next tile's staging
    }

    // Epilogue: normalize, stage O[i][d] into Ps, store transposed (d-major)
    float rl0 = 1.f / l0r, rl1 = 1.f / l1r;
#pragma unroll
    for (int nf = 0; nf < 8; nf++) {
        *(float2*)(&Ps[(i0 + g) * 68 + nf * 8 + tg * 2]) =
            make_float2(O[nf][0] * rl0, O[nf][1] * rl0);
        *(float2*)(&Ps[(i0 + g + 8) * 68 + nf * 8 + tg * 2]) =
            make_float2(O[nf][2] * rl1, O[nf][3] * rl1);
    }
    __syncthreads();
    float* ob = out + ((size_t)b * 512 + h * 64) * N_TOK;
#pragma unroll
    for (int e = tid; e < 64 * 32; e += 256) {
        int d = e >> 5, i4 = e & 31;
        float4 t = make_float4(Ps[(i4 * 4 + 0) * 68 + d], Ps[(i4 * 4 + 1) * 68 + d],
                               Ps[(i4 * 4 + 2) * 68 + d], Ps[(i4 * 4 + 3) * 68 + d]);
        *(float4*)(ob + (size_t)d * N_TOK + n0 + i4 * 4) = t;
    }
}

// ---------------------------------------------------------------------------
extern "C" void kernel_launch(void* const* d_in, const int* in_sizes, int n_in,
                              void* d_out, int out_size) {
    (void)in_sizes; (void)n_in; (void)out_size;
    const float* x      = (const float*)d_in[0];
    const float* w_qkv  = (const float*)d_in[1];
    const float* w_proj = (const float*)d_in[2];
    const float* b_proj = (const float*)d_in[3];
    float* y = (float*)d_out;

    float *qkv_p = nullptr, *inv_p = nullptr, *att_p = nullptr;
    cudaGetSymbolAddress((void**)&qkv_p, g_qkv);
    cudaGetSymbolAddress((void**)&inv_p, g_inv);
    cudaGetSymbolAddress((void**)&att_p, g_att);

    const int attn_smem = (128 * 68 + 64 * 68 + 64 * 68 + 128 * 68) * 4;  // 104448
    cudaFuncSetAttribute(attn_mma, cudaFuncAttributeMaxDynamicSharedMemorySize,
                         attn_smem);

    // 1) qkv = w_qkv @ x   (M=1536, K=256, N=2304, B=2)
    gemm_tf32<<<dim3(36, 12, 2), 256>>>(w_qkv, x, nullptr, qkv_p, 256, 12);
    // 2) inverse L2 norms
    norm_k<<<2048, 256>>>(qkv_p, inv_p);
    // 3) flash attention (tf32 mma)
    attn_mma<<<dim3(18, 8, 2), 256, attn_smem>>>(qkv_p, inv_p, att_p);
    // 4) y = w_proj @ att + b_proj   (M=256, K=512, N=2304, B=2)
    gemm_tf32<<<dim3(36, 2, 2), 256>>>(w_proj, att_p, b_proj, y, 512, 2);
}

// round 3
// speedup vs baseline: 4.4391x; 1.6571x over previous
#include <cuda_runtime.h>
#include <math.h>

#define N_TOK 2304

// Scratch (device globals: allocation-free per harness rules)
__device__ float g_qkv[2u * 1536u * 2304u];   // (B, 3*512, N)
__device__ float g_inv[2 * 1024];             // inv L2 norms: q rows 0..511, k rows 512..1023
__device__ float g_att[2u * 512u * 2304u];    // attention output (B, 512, N)
__device__ float g_w1[1536 * 256];            // tf32-rounded w_qkv
__device__ float g_w2[256 * 512];             // tf32-rounded w_proj

__device__ __forceinline__ float to_tf32(float x) {
    float r;
    asm("cvt.rna.tf32.f32 %0, %1;" : "=f"(r) : "f"(x));
    return r;
}
__device__ __forceinline__ unsigned fb(float x) { return __float_as_uint(x); }

__device__ __forceinline__ void mma_tf32(float* d, const unsigned* a, const unsigned* b) {
    asm volatile(
        "mma.sync.aligned.m16n8k8.row.col.f32.tf32.tf32.f32 "
        "{%0,%1,%2,%3}, {%4,%5,%6,%7}, {%8,%9}, {%0,%1,%2,%3};\n"
        : "+f"(d[0]), "+f"(d[1]), "+f"(d[2]), "+f"(d[3])
        : "r"(a[0]), "r"(a[1]), "r"(a[2]), "r"(a[3]), "r"(b[0]), "r"(b[1]));
}

__device__ __forceinline__ void cp16(unsigned dst, const void* src) {
    asm volatile("cp.async.ca.shared.global [%0], [%1], 16;" :: "r"(dst), "l"(src));
}
#define CP_COMMIT asm volatile("cp.async.commit_group;")
#define CP_WAIT(n) asm volatile("cp.async.wait_group %0;" :: "n"(n))

// ---------------------------------------------------------------------------
// Pre-round weights to tf32 (once, cheap)
// ---------------------------------------------------------------------------
__global__ void round_w(const float* __restrict__ a, const float* __restrict__ b,
                        float* __restrict__ wa, float* __restrict__ wb,
                        int na, int nb) {
    int i = blockIdx.x * 256 + threadIdx.x;
    if (i < na) wa[i] = to_tf32(a[i]);
    if (i < nb) wb[i] = to_tf32(b[i]);
}

// ---------------------------------------------------------------------------
// tf32 GEMM: Y[b][m][n] = sum_k W[m][k]*X[b][k][n] (+bias[m])
// Block tile BM x 128, 8 warps (4m x 2n), warp WM x 64, k-chunk 16, cp.async x2.
// W must be pre-rounded tf32; X fed raw (HW truncation).
// ---------------------------------------------------------------------------
template <int BM, int WM>
__global__ __launch_bounds__(256) void gemm2(
    const float* __restrict__ W, const float* __restrict__ X,
    const float* __restrict__ bias, float* __restrict__ Y, int K, int Mtot) {
    constexpr int NG = WM / 16;      // row groups per warp
    __shared__ float As[2][BM * 20];     // [m][k] stride 20
    __shared__ float Bs[2][16 * 136];    // [k][n] stride 136

    const int tid = threadIdx.x, lane = tid & 31, w = tid >> 5;
    const int g = lane >> 2, tg = lane & 3;
    const int wm0 = (w & 3) * WM, wn0 = (w >> 2) * 64;
    const int n0 = blockIdx.x * 128;
    const int m0 = blockIdx.y * BM;
    const int b  = blockIdx.z;
    const float* Xb = X + (size_t)b * K * N_TOK;
    float* Yb = Y + (size_t)b * Mtot * N_TOK;

    const unsigned sA = (unsigned)__cvta_generic_to_shared(&As[0][0]);
    const unsigned sB = (unsigned)__cvta_generic_to_shared(&Bs[0][0]);

    float acc[NG][8][4] = {};

    auto issue = [&](int k0, int buf) {
#pragma unroll
        for (int e = tid; e < BM * 4; e += 256) {
            int m = e >> 2, kq = e & 3;
            cp16(sA + (buf * BM * 20 + m * 20 + kq * 4) * 4,
                 W + (size_t)(m0 + m) * K + k0 + kq * 4);
        }
#pragma unroll
        for (int e = tid; e < 512; e += 256) {
            int kk = e >> 5, nq = e & 31;
            cp16(sB + (buf * 16 * 136 + kk * 136 + nq * 4) * 4,
                 Xb + (size_t)(k0 + kk) * N_TOK + n0 + nq * 4);
        }
        CP_COMMIT;
    };

    issue(0, 0);
    for (int k0 = 0; k0 < K; k0 += 16) {
        int buf = (k0 >> 4) & 1;
        if (k0 + 16 < K) { issue(k0 + 16, buf ^ 1); CP_WAIT(1); }
        else             { CP_WAIT(0); }
        __syncthreads();
        const float* Ab = As[buf];
        const float* Bb = Bs[buf];
#pragma unroll
        for (int kc = 0; kc < 16; kc += 8) {
            unsigned a[NG][4];
#pragma unroll
            for (int s = 0; s < NG; s++) {
                int r = wm0 + 16 * s + g;
                a[s][0] = fb(Ab[r * 20 + kc + tg]);
                a[s][1] = fb(Ab[(r + 8) * 20 + kc + tg]);
                a[s][2] = fb(Ab[r * 20 + kc + tg + 4]);
                a[s][3] = fb(Ab[(r + 8) * 20 + kc + tg + 4]);
            }
#pragma unroll
            for (int nf = 0; nf < 8; nf++) {
                unsigned bb[2];
                bb[0] = fb(Bb[(kc + tg) * 136 + wn0 + nf * 8 + g]);
                bb[1] = fb(Bb[(kc + tg + 4) * 136 + wn0 + nf * 8 + g]);
#pragma unroll
                for (int s = 0; s < NG; s++) mma_tf32(acc[s][nf], a[s], bb);
            }
        }
        __syncthreads();
    }
#pragma unroll
    for (int s = 0; s < NG; s++) {
        int r0 = m0 + wm0 + 16 * s + g, r1 = r0 + 8;
        float bv0 = bias ? bias[r0] : 0.f;
        float bv1 = bias ? bias[r1] : 0.f;
#pragma unroll
        for (int nf = 0; nf < 8; nf++) {
            *(float2*)(Yb + (size_t)r0 * N_TOK + n0 + wn0 + nf * 8 + tg * 2) =
                make_float2(acc[s][nf][0] + bv0, acc[s][nf][1] + bv0);
            *(float2*)(Yb + (size_t)r1 * N_TOK + n0 + wn0 + nf * 8 + tg * 2) =
                make_float2(acc[s][nf][2] + bv1, acc[s][nf][3] + bv1);
        }
    }
}

// ---------------------------------------------------------------------------
// Row L2-norm inverse
// ---------------------------------------------------------------------------
__global__ void norm_k(const float* __restrict__ qkv, float* __restrict__ inv) {
    const int row = blockIdx.x;            // 0..2047
    const int b = row >> 10, o = row & 1023;
    const float* p = qkv + ((size_t)b * 1536 + o) * N_TOK;
    float ss = 0.f;
    for (int i = threadIdx.x; i < N_TOK; i += 256) {
        float v = p[i];
        ss += v * v;
    }
#pragma unroll
    for (int off = 16; off; off >>= 1)
        ss += __shfl_xor_sync(0xffffffffu, ss, off);
    __shared__ float red[8];
    if ((threadIdx.x & 31) == 0) red[threadIdx.x >> 5] = ss;
    __syncthreads();
    if (threadIdx.x == 0) {
        float t = 0.f;
#pragma unroll
        for (int i = 0; i < 8; i++) t += red[i];
        inv[row] = 1.f / fmaxf(sqrtf(t), 1e-12f);
    }
}

// ---------------------------------------------------------------------------
// Flash attention v3: 256 queries/block, 8 warps x 32 rows, register-P,
// cp.async double-buffered K/V, scales folded into Q.
// Smem (floats): Qt2[64][264] | Ks[2][64][72] | Vs[2][64][68]
// ---------------------------------------------------------------------------
#define QT_STR 264
#define KS_STR 72
#define VS_STR 68
#define KS_OFF (64 * QT_STR)                     // 16896
#define VS_OFF (KS_OFF + 2 * 64 * KS_STR)        // 26112
#define ATTN_SMEM ((VS_OFF + 2 * 64 * VS_STR) * 4)  // 139264 B

__global__ __launch_bounds__(256, 1) void attn3(
    const float* __restrict__ qkv, const float* __restrict__ inv,
    float* __restrict__ out) {
    extern __shared__ float sm[];
    float* Qt = sm;
    float* KsBase = sm + KS_OFF;
    float* VsBase = sm + VS_OFF;

    const int tid = threadIdx.x, lane = tid & 31, w = tid >> 5;
    const int g = lane >> 2, tg = lane & 3;
    const int jj = (g >> 1) | ((g & 1) << 2);   // S-phase column permutation
    const int n0 = blockIdx.x * 256;
    const int h = blockIdx.y, b = blockIdx.z;
    const int i0 = w * 32;

    const float* qb = qkv + ((size_t)b * 1536 + h * 64) * N_TOK;
    const float* kb = qb + (size_t)512 * N_TOK;
    const float* vb = qb + (size_t)1024 * N_TOK;
    const float* invq = inv + b * 1024 + h * 64;
    const float* invk = invq + 512;

    const unsigned sBase = (unsigned)__cvta_generic_to_shared(sm);

    auto issueKV = [&](int t0, int buf) {
#pragma unroll
        for (int e = tid; e < 1024; e += 256) {
            int d = e >> 4, mq = e & 15;
            cp16(sBase + (KS_OFF + buf * 64 * KS_STR + d * KS_STR + mq * 4) * 4,
                 kb + (size_t)d * N_TOK + t0 + mq * 4);
            cp16(sBase + (VS_OFF + buf * 64 * VS_STR + d * VS_STR + mq * 4) * 4,
                 vb + (size_t)d * N_TOK + t0 + mq * 4);
        }
        CP_COMMIT;
    };

    issueKV(0, 0);

    // Stage Q d-major, scaled by invq*invk, rna-rounded. Conflict-free float4.
    for (int e = tid; e < 4096; e += 256) {
        int d = e >> 6, i4 = e & 63;
        float4 t = *(const float4*)(qb + (size_t)d * N_TOK + n0 + i4 * 4);
        float s = invq[d] * invk[d];
        float4 r = make_float4(to_tf32(t.x * s), to_tf32(t.y * s),
                               to_tf32(t.z * s), to_tf32(t.w * s));
        *(float4*)(&Qt[d * QT_STR + i4 * 4]) = r;
    }

    float O[2][8][4] = {};
    float mx[2][2] = {{-1e30f, -1e30f}, {-1e30f, -1e30f}};
    float ls[2][2] = {};

    for (int t0 = 0; t0 < N_TOK; t0 += 64) {
        int buf = (t0 >> 6) & 1;
        if (t0 + 64 < N_TOK) { issueKV(t0 + 64, buf ^ 1); CP_WAIT(1); }
        else                 { CP_WAIT(0); }
        __syncthreads();
        const float* Kb = KsBase + buf * 64 * KS_STR;
        const float* Vb = VsBase + buf * 64 * VS_STR;

        // S-phase: S[grp] = Q_rows x K (columns permuted by jj)
        float S[2][8][4] = {};
#pragma unroll
        for (int k0 = 0; k0 < 64; k0 += 8) {
            unsigned a[2][4];
#pragma unroll
            for (int grp = 0; grp < 2; grp++) {
                int r = i0 + 16 * grp + g;
                a[grp][0] = fb(Qt[(k0 + tg) * QT_STR + r]);
                a[grp][1] = fb(Qt[(k0 + tg) * QT_STR + r + 8]);
                a[grp][2] = fb(Qt[(k0 + tg + 4) * QT_STR + r]);
                a[grp][3] = fb(Qt[(k0 + tg + 4) * QT_STR + r + 8]);
            }
#pragma unroll
            for (int nf = 0; nf < 8; nf++) {
                unsigned bb[2];
                bb[0] = fb(Kb[(k0 + tg) * KS_STR + nf * 8 + jj]);
                bb[1] = fb(Kb[(k0 + tg + 4) * KS_STR + nf * 8 + jj]);
                mma_tf32(S[0][nf], a[0], bb);
                mma_tf32(S[1][nf], a[1], bb);
            }
        }

        // Online softmax (per grp: rows g [c0,c1] and g+8 [c2,c3])
#pragma unroll
        for (int grp = 0; grp < 2; grp++) {
            float r0 = -1e30f, r1 = -1e30f;
#pragma unroll
            for (int nf = 0; nf < 8; nf++) {
                r0 = fmaxf(r0, fmaxf(S[grp][nf][0], S[grp][nf][1]));
                r1 = fmaxf(r1, fmaxf(S[grp][nf][2], S[grp][nf][3]));
            }
            r0 = fmaxf(r0, __shfl_xor_sync(0xffffffffu, r0, 1));
            r0 = fmaxf(r0, __shfl_xor_sync(0xffffffffu, r0, 2));
            r1 = fmaxf(r1, __shfl_xor_sync(0xffffffffu, r1, 1));
            r1 = fmaxf(r1, __shfl_xor_sync(0xffffffffu, r1, 2));
            float mn0 = fmaxf(mx[grp][0], r0), mn1 = fmaxf(mx[grp][1], r1);
            float c0 = __expf(mx[grp][0] - mn0), c1 = __expf(mx[grp][1] - mn1);
            mx[grp][0] = mn0; mx[grp][1] = mn1;
            float s0 = 0.f, s1 = 0.f;
#pragma unroll
            for (int nf = 0; nf < 8; nf++) {
                S[grp][nf][0] = __expf(S[grp][nf][0] - mn0);
                S[grp][nf][1] = __expf(S[grp][nf][1] - mn0);
                S[grp][nf][2] = __expf(S[grp][nf][2] - mn1);
                S[grp][nf][3] = __expf(S[grp][nf][3] - mn1);
                s0 += S[grp][nf][0] + S[grp][nf][1];
                s1 += S[grp][nf][2] + S[grp][nf][3];
            }
            s0 += __shfl_xor_sync(0xffffffffu, s0, 1);
            s0 += __shfl_xor_sync(0xffffffffu, s0, 2);
            s1 += __shfl_xor_sync(0xffffffffu, s1, 1);
            s1 += __shfl_xor_sync(0xffffffffu, s1, 2);
            ls[grp][0] = ls[grp][0] * c0 + s0;
            ls[grp][1] = ls[grp][1] * c1 + s1;
#pragma unroll
            for (int nf = 0; nf < 8; nf++) {
                O[grp][nf][0] *= c0; O[grp][nf][1] *= c0;
                O[grp][nf][2] *= c1; O[grp][nf][3] *= c1;
                S[grp][nf][0] = to_tf32(S[grp][nf][0]);
                S[grp][nf][1] = to_tf32(S[grp][nf][1]);
                S[grp][nf][2] = to_tf32(S[grp][nf][2]);
                S[grp][nf][3] = to_tf32(S[grp][nf][3]);
            }
        }

        // PV-phase: A = P (registers, via permutation identity), B = V^T
#pragma unroll
        for (int kk = 0; kk < 8; kk++) {
            unsigned pa[2][4];
#pragma unroll
            for (int grp = 0; grp < 2; grp++) {
                pa[grp][0] = fb(S[grp][kk][0]);
                pa[grp][1] = fb(S[grp][kk][2]);
                pa[grp][2] = fb(S[grp][kk][1]);
                pa[grp][3] = fb(S[grp][kk][3]);
            }
#pragma unroll
            for (int nf = 0; nf < 8; nf++) {
                unsigned bb[2];
                bb[0] = fb(Vb[(nf * 8 + g) * VS_STR + kk * 8 + tg]);
                bb[1] = fb(Vb[(nf * 8 + g) * VS_STR + kk * 8 + tg + 4]);
                mma_tf32(O[0][nf], pa[0], bb);
                mma_tf32(O[1][nf], pa[1], bb);
            }
        }
        __syncthreads();
    }

    // Epilogue: normalize, stage d-major via smem (reuse Ks region), store.
    float* Os = KsBase;   // 64 x 136
    float* ob = out + ((size_t)b * 512 + h * 64) * N_TOK;
#pragma unroll
    for (int pass = 0; pass < 2; pass++) {
        __syncthreads();
        if ((w >> 2) == pass) {
            int base = (w & 3) * 32;
#pragma unroll
            for (int grp = 0; grp < 2; grp++) {
                float rl0 = 1.f / ls[grp][0], rl1 = 1.f / ls[grp][1];
                int ir0 = base + 16 * grp + g, ir1 = ir0 + 8;
#pragma unroll
                for (int nf = 0; nf < 8; nf++) {
                    int d0 = nf * 8 + 2 * tg;
                    Os[d0 * 136 + ir0]       = O[grp][nf][0] * rl0;
                    Os[(d0 + 1) * 136 + ir0] = O[grp][nf][1] * rl0;
                    Os[d0 * 136 + ir1]       = O[grp][nf][2] * rl1;
                    Os[(d0 + 1) * 136 + ir1] = O[grp][nf][3] * rl1;
                }
            }
        }
        __syncthreads();
        for (int e = tid; e < 2048; e += 256) {
            int d = e >> 5, i4 = e & 31;
            float4 t = *(const float4*)(&Os[d * 136 + i4 * 4]);
            *(float4*)(ob + (size_t)d * N_TOK + n0 + pass * 128 + i4 * 4) = t;
        }
    }
}

// ---------------------------------------------------------------------------
extern "C" void kernel_launch(void* const* d_in, const int* in_sizes, int n_in,
                              void* d_out, int out_size) {
    (void)in_sizes; (void)n_in; (void)out_size;
    const float* x      = (const float*)d_in[0];
    const float* w_qkv  = (const float*)d_in[1];
    const float* w_proj = (const float*)d_in[2];
    const float* b_proj = (const float*)d_in[3];
    float* y = (float*)d_out;

    float *qkv_p, *inv_p, *att_p, *w1_p, *w2_p;
    cudaGetSymbolAddress((void**)&qkv_p, g_qkv);
    cudaGetSymbolAddress((void**)&inv_p, g_inv);
    cudaGetSymbolAddress((void**)&att_p, g_att);
    cudaGetSymbolAddress((void**)&w1_p, g_w1);
    cudaGetSymbolAddress((void**)&w2_p, g_w2);

    cudaFuncSetAttribute(attn3, cudaFuncAttributeMaxDynamicSharedMemorySize,
                         ATTN_SMEM);

    // 0) pre-round weights to tf32
    round_w<<<1536, 256>>>(w_qkv, w_proj, w1_p, w2_p, 1536 * 256, 256 * 512);
    // 1) qkv = w_qkv @ x   (M=1536, K=256)
    gemm2<128, 32><<<dim3(18, 12, 2), 256>>>(w1_p, x, nullptr, qkv_p, 256, 1536);
    // 2) inverse L2 norms
    norm_k<<<2048, 256>>>(qkv_p, inv_p);
    // 3) flash attention
    attn3<<<dim3(9, 8, 2), 256, ATTN_SMEM>>>(qkv_p, inv_p, att_p);
    // 4) y = w_proj @ att + b_proj   (M=256, K=512)
    gemm2<64, 16><<<dim3(18, 4, 2), 256>>>(w2_p, att_p, b_proj, y, 512, 256);
}